// round 6
// baseline (speedup 1.0000x reference)
#include <cuda_runtime.h>
#include <cstdint>

// ShapeIndex over (B=16, C=1, H=1536, W=1536) fp32 — packed f32x2 version.
// si = (2/pi)*asin(t),  t = -N1 * rsqrt(2*N1^2 - 4*u*N2)
//   N1 = (1+q^2)r - 2pqs + (1+p^2)t, N2 = r*t - s^2, u = 1+p^2+q^2
// asin via A&S 4.4.45 (2/pi folded): sign(t)*(1 - sqrt(1-|t|)*P(|t|)).
// All FMA-pipe math done 2 elements/instruction via fma/add/mul.rn.f32x2 (FFMA2).

#define BB 16
#define HH 1536
#define WW 1536
#define W4 (WW / 4)

typedef unsigned long long u64;

__device__ __forceinline__ u64 pk2(float lo, float hi) {
    u64 r; asm("mov.b64 %0, {%1, %2};" : "=l"(r) : "f"(lo), "f"(hi)); return r;
}
__device__ __forceinline__ void upk2(u64 v, float& lo, float& hi) {
    asm("mov.b64 {%0, %1}, %2;" : "=f"(lo), "=f"(hi) : "l"(v));
}
__device__ __forceinline__ u64 f2fma(u64 a, u64 b, u64 c) {
    u64 r; asm("fma.rn.f32x2 %0, %1, %2, %3;" : "=l"(r) : "l"(a), "l"(b), "l"(c)); return r;
}
__device__ __forceinline__ u64 f2mul(u64 a, u64 b) {
    u64 r; asm("mul.rn.f32x2 %0, %1, %2;" : "=l"(r) : "l"(a), "l"(b)); return r;
}
__device__ __forceinline__ u64 f2add(u64 a, u64 b) {
    u64 r; asm("add.rn.f32x2 %0, %1, %2;" : "=l"(r) : "l"(a), "l"(b)); return r;
}
__device__ __forceinline__ u64 f2and(u64 a, u64 m) {
    u64 r; asm("and.b64 %0, %1, %2;" : "=l"(r) : "l"(a), "l"(m)); return r;
}

// packed constants (each half = same fp32 value)
#define ONE2   0x3F8000003F800000ull   //  1.0
#define NEG1_2 0xBF800000BF800000ull   // -1.0
#define NEG2_2 0xC0000000C0000000ull   // -2.0
#define NEG4_2 0xC0800000C0800000ull   // -4.0
#define ABSM   0x7FFFFFFF7FFFFFFFull

__device__ __forceinline__ float sqrt_approx(float x) {
    float r; asm("sqrt.approx.f32 %0, %1;" : "=f"(r) : "f"(x)); return r;
}
__device__ __forceinline__ float remove_nan(float v) {
    unsigned u = __float_as_uint(v);
    return ((u & 0x7fffffffu) > 0x7f800000u) ? 0.0f : v;
}

// a - b  ==  fma(b, -1, a)   (exact: product is exact, one rounding like sub.rn)
__device__ __forceinline__ u64 f2sub(u64 a, u64 b) { return f2fma(b, NEG1_2, a); }

// Compute shape index for 2 elements packed in f32x2 lanes.
__device__ __forceinline__ void si_pair(u64 xc, u64 xh1, u64 xh2,
                                        u64 xm1, u64 xm2, u64 xh1m1,
                                        float& o0, float& o1) {
    const u64 C3 = pk2(-0.0119235f, -0.0119235f);
    const u64 C2 = pk2( 0.0472761f,  0.0472761f);
    const u64 C1 = pk2(-0.1350363f, -0.1350363f);
    const u64 C0 = pk2( 0.9999570f,  0.9999570f);

    u64 p  = f2sub(xh1, xc);
    u64 q  = f2sub(xm1, xc);
    u64 r  = f2sub(f2sub(xh2, xh1), p);
    u64 t  = f2sub(f2sub(xm2, xm1), q);
    u64 s  = f2sub(f2sub(xh1m1, xm1), p);

    u64 a  = f2fma(q, q, ONE2);            // 1+q^2
    u64 b  = f2fma(p, p, ONE2);            // 1+p^2
    u64 u  = f2fma(p, p, a);               // 1+p^2+q^2
    u64 pq = f2mul(p, q);
    u64 w  = f2mul(pq, s);                 // pqs
    u64 N1 = f2fma(a, r, f2fma(b, t, f2mul(w, NEG2_2)));
    u64 ss = f2mul(s, s);
    u64 N2 = f2fma(ss, NEG1_2, f2mul(r, t));
    u64 un2  = f2mul(u, N2);
    u64 n1x2 = f2add(N1, N1);
    u64 den  = f2fma(n1x2, N1, f2mul(un2, NEG4_2));  // 2*N1^2 - 4*u*N2

    float d0, d1; upk2(den, d0, d1);
    u64 rsq = pk2(rsqrtf(d0), rsqrtf(d1));
    u64 tt  = f2mul(f2mul(N1, NEG1_2), rsq);          // -N1/sqrt(den)

    u64 aa   = f2and(tt, ABSM);                       // |t|
    u64 poly = f2fma(f2fma(f2fma(C3, aa, C2), aa, C1), aa, C0);
    u64 om   = f2fma(aa, NEG1_2, ONE2);               // 1-|t|
    float m0, m1; upk2(om, m0, m1);
    u64 sq   = pk2(sqrt_approx(m0), sqrt_approx(m1)); // NaN if |t|>1 -> si=0
    u64 mag  = f2fma(f2mul(sq, poly), NEG1_2, ONE2);  // (2/pi)*asin(|t|)

    float g0, g1, t0, t1;
    upk2(mag, g0, g1);
    upk2(tt,  t0, t1);
    o0 = remove_nan(copysignf(g0, t0));
    o1 = remove_nan(copysignf(g1, t1));
}

__global__ __launch_bounds__(W4)
void si_kernel(const float* __restrict__ x, float* __restrict__ out) {
    const int w4 = threadIdx.x;          // 0..383
    const int h  = blockIdx.x;           // 0..1535
    const int b  = blockIdx.y;           // 0..15
    const int w0 = w4 * 4;

    const float* img = x + (size_t)b * (HH * WW);
    const int hm1 = (h == 0) ? HH - 1 : h - 1;
    const int hm2 = (hm1 == 0) ? HH - 1 : hm1 - 1;

    const float* rowh  = img + h   * WW;
    const float* rowh1 = img + hm1 * WW;
    const float* rowh2 = img + hm2 * WW;

    float4 a  = *reinterpret_cast<const float4*>(rowh  + w0);
    float4 c1 = *reinterpret_cast<const float4*>(rowh1 + w0);
    float4 c2 = *reinterpret_cast<const float4*>(rowh2 + w0);

    const int wm1 = (w0 == 0) ? WW - 1 : w0 - 1;
    const int wm2 = (w0 == 0) ? WW - 2 : w0 - 2;
    float am1  = rowh[wm1];
    float am2  = rowh[wm2];
    float c1m1 = rowh1[wm1];

    float4 o;
    // pair (x, y): taps at w-1 = {am1, a.x}, w-2 = {am2, am1}, diag = {c1m1, c1.x}
    si_pair(pk2(a.x, a.y), pk2(c1.x, c1.y), pk2(c2.x, c2.y),
            pk2(am1, a.x), pk2(am2, am1), pk2(c1m1, c1.x), o.x, o.y);
    // pair (z, w): taps at w-1 = {a.y, a.z}, w-2 = {a.x, a.y}, diag = {c1.y, c1.z}
    si_pair(pk2(a.z, a.w), pk2(c1.z, c1.w), pk2(c2.z, c2.w),
            pk2(a.y, a.z), pk2(a.x, a.y), pk2(c1.y, c1.z), o.z, o.w);

    float* orow = out + ((size_t)b * HH + h) * WW;
    *reinterpret_cast<float4*>(orow + w0) = o;
}

extern "C" void kernel_launch(void* const* d_in, const int* in_sizes, int n_in,
                              void* d_out, int out_size) {
    const float* x = (const float*)d_in[0];
    float* out = (float*)d_out;
    dim3 grid(HH, BB, 1);    // h, b
    si_kernel<<<grid, W4>>>(x, out);
}

// round 7
// speedup vs baseline: 1.1010x; 1.1010x over previous
#include <cuda_runtime.h>
#include <cstdint>

// ShapeIndex over (B=16, C=1, H=1536, W=1536) fp32.
// si = (2/pi)*asin(t),  t = -N1 * rsqrt(2*N1^2 - 4*u*N2)
//   N1 = (1+q^2)r - 2pqs + (1+p^2)t, N2 = r*t - s^2, u = 1+p^2+q^2
// Shared horizontal differences: e(w)=x[w-1]-x[w], p(w)=xh1[w]-x[w];
//   q=e(w), t=e(w-1)-e(w), s=p(w-1)-p(w)  (identical to reference roll-diffs).
// asin via A&S 4.4.45 with 2/pi folded in.

#define BB 16
#define HH 1536
#define WW 1536
#define EPT 8                 // elements per thread
#define TPB (WW / EPT)        // 192 threads, one row per block

__device__ __forceinline__ float remove_nan(float v) {
    unsigned u = __float_as_uint(v);
    return ((u & 0x7fffffffu) > 0x7f800000u) ? 0.0f : v;
}
__device__ __forceinline__ float sqrt_approx(float x) {
    float r; asm("sqrt.approx.f32 %0, %1;" : "=f"(r) : "f"(x)); return r;
}

// Elementwise tail given first/second differences.
__device__ __forceinline__ float si_tail(float p, float q, float r, float t, float s) {
    float p2 = p * p;
    float a  = fmaf(q, q, 1.0f);        // 1+q^2
    float b  = p2 + 1.0f;               // 1+p^2
    float u  = a + p2;                  // 1+p^2+q^2
    float pqs = (p * q) * s;
    float N1 = fmaf(a, r, fmaf(b, t, -2.0f * pqs));
    float N2 = fmaf(r, t, -(s * s));
    float den = fmaf(2.0f * N1, N1, -4.0f * u * N2);   // N1^2 + D
    float tt  = -N1 * rsqrtf(den);
    float aa  = fabsf(tt);
    float poly = fmaf(fmaf(fmaf(-0.0119235f, aa, 0.0472761f),
                           aa, -0.1350363f), aa, 0.9999570f);
    float mag = fmaf(-sqrt_approx(1.0f - aa), poly, 1.0f);  // (2/pi)asin(|t|)
    return remove_nan(copysignf(mag, tt));
}

__global__ __launch_bounds__(TPB)
void si_kernel(const float* __restrict__ x, float* __restrict__ out) {
    const int tid = threadIdx.x;         // 0..191
    const int h   = blockIdx.x;          // 0..1535
    const int b   = blockIdx.y;          // 0..15
    const int w0  = tid * EPT;

    const float* img = x + (size_t)b * (HH * WW);
    const int hm1 = (h == 0) ? HH - 1 : h - 1;
    const int hm2 = (hm1 == 0) ? HH - 1 : hm1 - 1;

    const float* rowh  = img + h   * WW;
    const float* rowh1 = img + hm1 * WW;
    const float* rowh2 = img + hm2 * WW;

    float a[EPT], c1[EPT], c2[EPT];
    {
        float4 v0 = *reinterpret_cast<const float4*>(rowh  + w0);
        float4 v1 = *reinterpret_cast<const float4*>(rowh  + w0 + 4);
        a[0]=v0.x; a[1]=v0.y; a[2]=v0.z; a[3]=v0.w;
        a[4]=v1.x; a[5]=v1.y; a[6]=v1.z; a[7]=v1.w;
        float4 u0 = *reinterpret_cast<const float4*>(rowh1 + w0);
        float4 u1 = *reinterpret_cast<const float4*>(rowh1 + w0 + 4);
        c1[0]=u0.x; c1[1]=u0.y; c1[2]=u0.z; c1[3]=u0.w;
        c1[4]=u1.x; c1[5]=u1.y; c1[6]=u1.z; c1[7]=u1.w;
        float4 t0 = *reinterpret_cast<const float4*>(rowh2 + w0);
        float4 t1 = *reinterpret_cast<const float4*>(rowh2 + w0 + 4);
        c2[0]=t0.x; c2[1]=t0.y; c2[2]=t0.z; c2[3]=t0.w;
        c2[4]=t1.x; c2[5]=t1.y; c2[6]=t1.z; c2[7]=t1.w;
    }

    const int wm1 = (w0 == 0) ? WW - 1 : w0 - 1;
    const int wm2 = (w0 == 0) ? WW - 2 : w0 - 2;
    const float am1  = rowh[wm1];   // x[h][w0-1]
    const float am2  = rowh[wm2];   // x[h][w0-2]
    const float c1m1 = rowh1[wm1];  // x[h-1][w0-1]

    // Shared horizontal difference chains (indices -1..EPT-1 mapped to 0..EPT)
    float e[EPT + 1], p[EPT + 1];
    e[0] = am2 - am1;                  // e(w0-1)
    e[1] = am1 - a[0];                 // e(w0)
    p[0] = c1m1 - am1;                 // p(w0-1)
#pragma unroll
    for (int i = 0; i < EPT; i++) p[i + 1] = c1[i] - a[i];
#pragma unroll
    for (int i = 1; i < EPT; i++) e[i + 1] = a[i - 1] - a[i];

    float o[EPT];
#pragma unroll
    for (int i = 0; i < EPT; i++) {
        float pp = p[i + 1];
        float qq = e[i + 1];
        float rr = (c2[i] - c1[i]) - pp;   // vertical 2nd diff
        float tt = e[i] - e[i + 1];        // horizontal 2nd diff
        float ss = p[i] - p[i + 1];        // cross diff
        o[i] = si_tail(pp, qq, rr, tt, ss);
    }

    float* orow = out + ((size_t)b * HH + h) * WW;
    float4 s0 = make_float4(o[0], o[1], o[2], o[3]);
    float4 s1 = make_float4(o[4], o[5], o[6], o[7]);
    *reinterpret_cast<float4*>(orow + w0)     = s0;
    *reinterpret_cast<float4*>(orow + w0 + 4) = s1;
}

extern "C" void kernel_launch(void* const* d_in, const int* in_sizes, int n_in,
                              void* d_out, int out_size) {
    const float* x = (const float*)d_in[0];
    float* out = (float*)d_out;
    dim3 grid(HH, BB, 1);
    si_kernel<<<grid, TPB>>>(x, out);
}

// round 8
// speedup vs baseline: 1.2071x; 1.0963x over previous
#include <cuda_runtime.h>
#include <cstdint>

// ShapeIndex over (B=16, C=1, H=1536, W=1536) fp32 — rolling-row version.
// si = (2/pi)*asin(t),  t = -N1 * rsqrt(2*N1^2 - 4*u*N2)
//   N1 = (1+q^2)r - 2pqs + (1+p^2)t, N2 = r*t - s^2, u = 1+p^2+q^2
// Difference identities (exactly the reference roll-diffs):
//   P[h][w] = x[h-1][w]-x[h][w]  (vertical 1st diff == reference p)
//   e[h][w] = x[h][w-1]-x[h][w]  (horizontal 1st diff == reference q)
//   r = P[h-1]-P[h],  t = e[w-1]-e[w],  s = P[w-1]-P[w]
// A block walks ROWS consecutive rows, carrying P/prev in registers:
// one new input row loaded per output row (vs 3 in the naive scheme).

#define BB 16
#define HH 1536
#define WW 1536
#define EPT 8                  // elements (columns) per thread
#define TPB (WW / EPT)         // 192 threads: one full row per block-row-step
#define ROWS 8                 // rows per block

__device__ __forceinline__ float remove_nan(float v) {
    unsigned u = __float_as_uint(v);
    return ((u & 0x7fffffffu) > 0x7f800000u) ? 0.0f : v;
}
__device__ __forceinline__ float sqrt_approx(float x) {
    float r; asm("sqrt.approx.f32 %0, %1;" : "=f"(r) : "f"(x)); return r;
}

__device__ __forceinline__ float si_tail(float p, float q, float r, float t, float s) {
    float p2 = p * p;
    float a  = fmaf(q, q, 1.0f);        // 1+q^2
    float b  = p2 + 1.0f;               // 1+p^2
    float u  = a + p2;                  // 1+p^2+q^2
    float pqs = (p * q) * s;
    float N1 = fmaf(a, r, fmaf(b, t, -2.0f * pqs));
    float N2 = fmaf(r, t, -(s * s));
    float den = fmaf(2.0f * N1, N1, -4.0f * u * N2);   // N1^2 + D
    float tt  = -N1 * rsqrtf(den);
    float aa  = fabsf(tt);
    float poly = fmaf(fmaf(fmaf(-0.0119235f, aa, 0.0472761f),
                           aa, -0.1350363f), aa, 0.9999570f);
    float mag = fmaf(-sqrt_approx(1.0f - aa), poly, 1.0f);  // (2/pi)asin(|t|)
    return remove_nan(copysignf(mag, tt));
}

__device__ __forceinline__ void load8(const float* __restrict__ row, int w0, float* v) {
    float4 v0 = *reinterpret_cast<const float4*>(row + w0);
    float4 v1 = *reinterpret_cast<const float4*>(row + w0 + 4);
    v[0]=v0.x; v[1]=v0.y; v[2]=v0.z; v[3]=v0.w;
    v[4]=v1.x; v[5]=v1.y; v[6]=v1.z; v[7]=v1.w;
}

__global__ __launch_bounds__(TPB)
void si_kernel(const float* __restrict__ x, float* __restrict__ out) {
    const int tid = threadIdx.x;            // 0..191
    const int h0  = blockIdx.x * ROWS;      // first output row of this block
    const int b   = blockIdx.y;             // 0..15
    const int w0  = tid * EPT;
    const int wm1 = (w0 == 0) ? WW - 1 : w0 - 1;
    const int wm2 = (w0 == 0) ? WW - 2 : w0 - 2;

    const float* img = x + (size_t)b * (HH * WW);
    float* oimg = out + (size_t)b * (HH * WW);

    const int hm1 = (h0 == 0) ? HH - 1 : h0 - 1;
    const int hm2 = (hm1 == 0) ? HH - 1 : hm1 - 1;

    // Prime: prev = row h0-1 (+ its w0-1 scalar), Pprev = row(h0-1)'s vertical diff.
    float prev[EPT], Pprev[EPT];
    load8(img + (size_t)hm1 * WW, w0, prev);
    float prevm1 = img[(size_t)hm1 * WW + wm1];
    {
        float tmp[EPT];
        load8(img + (size_t)hm2 * WW, w0, tmp);
#pragma unroll
        for (int i = 0; i < EPT; i++) Pprev[i] = tmp[i] - prev[i];
    }

#pragma unroll
    for (int j = 0; j < ROWS; j++) {
        const int h = h0 + j;
        const float* rowh = img + (size_t)h * WW;

        float cur[EPT];
        load8(rowh, w0, cur);
        float am1 = rowh[wm1];
        float am2 = rowh[wm2];

        // vertical 1st diffs for this row (indices: P[0] = col w0-1, P[i+1] = col w0+i)
        float P[EPT + 1];
        P[0] = prevm1 - am1;
#pragma unroll
        for (int i = 0; i < EPT; i++) P[i + 1] = prev[i] - cur[i];

        float o[EPT];
        float eprev = am2 - am1;          // e(w0-1)
        float ecur  = am1 - cur[0];       // e(w0)
#pragma unroll
        for (int i = 0; i < EPT; i++) {
            float qq = ecur;
            float tt = eprev - ecur;               // horizontal 2nd diff
            float ss = P[i] - P[i + 1];            // cross diff
            float rr = Pprev[i] - P[i + 1];        // vertical 2nd diff
            o[i] = si_tail(P[i + 1], qq, rr, tt, ss);
            eprev = ecur;
            if (i < EPT - 1) ecur = cur[i] - cur[i + 1];
        }

        float* orow = oimg + (size_t)h * WW;
        *reinterpret_cast<float4*>(orow + w0)     = make_float4(o[0], o[1], o[2], o[3]);
        *reinterpret_cast<float4*>(orow + w0 + 4) = make_float4(o[4], o[5], o[6], o[7]);

        // roll state to next row
#pragma unroll
        for (int i = 0; i < EPT; i++) { Pprev[i] = P[i + 1]; prev[i] = cur[i]; }
        prevm1 = am1;
    }
}

extern "C" void kernel_launch(void* const* d_in, const int* in_sizes, int n_in,
                              void* d_out, int out_size) {
    const float* x = (const float*)d_in[0];
    float* out = (float*)d_out;
    dim3 grid(HH / ROWS, BB, 1);   // 192 x 16 blocks
    si_kernel<<<grid, TPB>>>(x, out);
}